// round 16
// baseline (speedup 1.0000x reference)
#include <cuda_runtime.h>
#include <cuda_fp16.h>
#include <math.h>
#include <stdint.h>

#define B   8
#define C   512
#define CH  256
#define P   4096
#define LN_EPS 1e-6f

#define TM 128
#define TN 128
#define KS 32
#define NSTAGE (C / KS)
#define NPIPE 4

#define RSB 80
#define TILE_BYTES (128 * RSB)
#define OFF_A 0
#define OFF_B (TILE_BYTES)
#define STAGE_BYTES (2 * TILE_BYTES)
#define SMEM_GEMM_BYTES (NPIPE * STAGE_BYTES)  // 81920
#define TEP 132

#define NBLK 256   // fused-kernel grid size (all co-resident: 148 SMs x >=2 CTAs)

// scratch
__device__ float d_gpart[P/32][B*C];
__device__ float d_sppart16[C/32][B*P];
__device__ float d_g[B*C];
__device__ float d_sp[B*P];
__device__ float d_ssp[B];
__device__ float d_t1[B*CH];
__device__ float d_t2[B*C];
__device__ float d_s1[B*CH];
__device__ float d_u2[B*C];
__device__ float d_ca[B*C];
__device__ float d_sumpar[B*C];
__device__ float d_a[B*C];
__device__ float d_S[B*C];
__device__ __half d_xh[(size_t)B*P*C];
__device__ __half d_wh[C*C];

// software grid barrier state (monotonic generation; count self-resets)
__device__ int d_bar_cnt = 0;
__device__ volatile int d_bar_gen = 0;

__device__ __forceinline__ float hsig(float v) {
    return fminf(fmaxf((v + 3.0f) * (1.0f/6.0f), 0.0f), 1.0f);
}

__device__ __forceinline__ uint32_t smem_u32(const void* p) {
    uint32_t a;
    asm("{ .reg .u64 t; cvta.to.shared.u64 t, %1; cvt.u32.u64 %0, t; }" : "=r"(a) : "l"(p));
    return a;
}
#define CP16(dst, src) \
    asm volatile("cp.async.cg.shared.global [%0], [%1], 16;" :: "r"(dst), "l"(src))
#define CP_COMMIT() asm volatile("cp.async.commit_group;" ::: "memory")
#define CP_WAIT(n)  asm volatile("cp.async.wait_group %0;" :: "n"(n) : "memory")

__device__ __forceinline__ void ldsm_x4(uint32_t& r0, uint32_t& r1, uint32_t& r2,
                                        uint32_t& r3, uint32_t addr) {
    asm volatile("ldmatrix.sync.aligned.m8n8.x4.shared.b16 {%0,%1,%2,%3}, [%4];"
                 : "=r"(r0), "=r"(r1), "=r"(r2), "=r"(r3) : "r"(addr));
}

__device__ __forceinline__ void mma16816(float* c, const uint32_t* a,
                                         uint32_t b0, uint32_t b1) {
    asm volatile(
        "mma.sync.aligned.m16n8k16.row.col.f32.f16.f16.f32 "
        "{%0,%1,%2,%3}, {%4,%5,%6,%7}, {%8,%9}, {%0,%1,%2,%3};"
        : "+f"(c[0]), "+f"(c[1]), "+f"(c[2]), "+f"(c[3])
        : "r"(a[0]), "r"(a[1]), "r"(a[2]), "r"(a[3]), "r"(b0), "r"(b1));
}

__device__ __forceinline__ float warp_red(float v) {
    #pragma unroll
    for (int o = 16; o > 0; o >>= 1) v += __shfl_down_sync(0xffffffffu, v, o);
    return v;
}

// grid barrier: sense-reversing, all NBLK blocks must be co-resident
__device__ __forceinline__ void grid_bar() {
    __syncthreads();
    if (threadIdx.x == 0) {
        __threadfence();
        int g = d_bar_gen;
        if (atomicAdd(&d_bar_cnt, 1) == NBLK - 1) {
            d_bar_cnt = 0;
            __threadfence();
            d_bar_gen = g + 1;
        } else {
            while (d_bar_gen == g) { __nanosleep(32); }
        }
        __threadfence();
    }
    __syncthreads();
}

// ---------------------------------------------------------------------------
// K_X: ONE pass over x -> xh transpose + channel-sum partials + spatial partials
__global__ void k_xpass(const float* __restrict__ x, const float* __restrict__ w1) {
    __shared__ float tile[32][33];
    __shared__ float red[8][32];
    __shared__ float w1s[32];
    int b = blockIdx.z, c0 = blockIdx.y * 32, p0 = blockIdx.x * 32;
    int tx = threadIdx.x, ty = threadIdx.y;
    if (ty == 0) w1s[tx] = w1[c0 + tx];
    #pragma unroll
    for (int i = 0; i < 4; i++) {
        int cl = ty + i * 8;
        tile[cl][tx] = x[((size_t)b * C + c0 + cl) * P + p0 + tx];
    }
    __syncthreads();
    #pragma unroll
    for (int i = 0; i < 4; i++) {
        int pl = ty + i * 8;
        d_xh[((size_t)b * P + p0 + pl) * C + c0 + tx] = __float2half(tile[tx][pl]);
    }
    #pragma unroll
    for (int i = 0; i < 4; i++) {
        int cl = ty + i * 8;
        float v = warp_red(tile[cl][tx]);
        if (tx == 0) d_gpart[blockIdx.x][b * C + c0 + cl] = v;
    }
    {
        float acc = 0.f;
        #pragma unroll
        for (int i = 0; i < 4; i++) {
            int cl = ty + i * 8;
            acc += tile[cl][tx] * w1s[cl];
        }
        red[ty][tx] = acc; __syncthreads();
        if (ty < 4) red[ty][tx] += red[ty + 4][tx];
        __syncthreads();
        if (ty < 2) red[ty][tx] += red[ty + 2][tx];
        __syncthreads();
        if (ty == 0) d_sppart16[blockIdx.y][b * P + p0 + tx] = red[0][tx] + red[1][tx];
    }
}

__global__ void k_convert_w(const float* __restrict__ res_w) {
    int i = blockIdx.x * 256 + threadIdx.x;
    d_wh[i] = __float2half(res_w[i]);
}

// ---------------------------------------------------------------------------
// K_FUSED: gfin | spfin_ssp -> mlp1 -> mlp2 -> ln -> sumpar -> sel1 -> sel2 -> sel3
// grid = NBLK(256) blocks x 256 threads, software grid barriers between phases.
__global__ void __launch_bounds__(256, 2)
k_fused(const float* __restrict__ w_b1, const float* __restrict__ b_b1,
        const float* __restrict__ w_b2, const float* __restrict__ b_b2,
        const float* __restrict__ ln_g, const float* __restrict__ ln_b,
        const float* __restrict__ sk_w1, const float* __restrict__ sk_w2) {
    __shared__ float sps[P];       // 16 KB, reused across phases
    __shared__ float aux[640];     // small staging / reductions
    const int blk = blockIdx.x;
    const int tid = threadIdx.x;
    const int wd = tid >> 5, lane = tid & 31;

    // ---- phase A: blocks 0..63 gfin, blocks 64..71 spfin+ssp ----
    if (blk < 64) {
        int li = tid & 63, q = tid >> 6;
        int i = blk * 64 + li;
        float s = 0.f;
        #pragma unroll
        for (int t = 0; t < 32; t++) s += d_gpart[q * 32 + t][i];
        aux[q * 64 + li] = s;
        __syncthreads();
        if (q == 0) d_g[i] = aux[li] + aux[64 + li] + aux[128 + li] + aux[192 + li];
    } else if (blk < 72) {
        int b = blk - 64;
        float s = 0.f;
        #pragma unroll
        for (int t = 0; t < P / 256; t++) {
            int i = b * P + t * 256 + tid;
            float v = 0.f;
            #pragma unroll
            for (int q = 0; q < C / 32; q++) v += d_sppart16[q][i];
            v = hsig(v);
            d_sp[i] = v;
            s += v;
        }
        aux[tid] = s; __syncthreads();
        for (int o = 128; o > 0; o >>= 1) { if (tid < o) aux[tid] += aux[tid + o]; __syncthreads(); }
        if (tid == 0) d_ssp[b] = aux[0];
    }
    grid_bar();

    // ---- phase B: mlp1 — blk = jg*8 + b ----
    {
        int b = blk & 7, jg = blk >> 3;
        for (int i = tid; i < C; i += 256) sps[i] = d_g[b * C + i] * (1.0f / P);
        __syncthreads();
        int j = jg * 8 + wd;
        const float* wr = w_b1 + (size_t)j * C;
        float acc = 0.f;
        #pragma unroll
        for (int k = 0; k < C / 32; k++) acc += sps[lane + 32 * k] * wr[lane + 32 * k];
        acc = warp_red(acc);
        if (lane == 0) d_t1[b * CH + j] = fmaxf(acc + b_b1[j], 0.f);
    }
    grid_bar();

    // ---- phase C: mlp2 — each warp does 2 outputs ----
    {
        int b = blk & 7, jg = blk >> 3;
        for (int i = tid; i < CH; i += 256) sps[i] = d_t1[b * CH + i];
        __syncthreads();
        #pragma unroll
        for (int h = 0; h < 2; h++) {
            int j = jg * 16 + h * 8 + wd;
            const float* wr = w_b2 + (size_t)j * CH;
            float acc = 0.f;
            #pragma unroll
            for (int k = 0; k < CH / 32; k++) acc += sps[lane + 32 * k] * wr[lane + 32 * k];
            acc = warp_red(acc);
            if (lane == 0) d_t2[b * C + j] = hsig(acc + b_b2[j]);
        }
    }
    grid_bar();

    // ---- phase D: layernorm — blocks 0..7 ----
    if (blk < 8) {
        int b = blk;
        for (int j = tid; j < C; j += 256) sps[j] = d_t2[b * C + j];
        __syncthreads();
        float s = 0.f;
        for (int j = tid; j < C; j += 256) s += sps[j];
        aux[tid] = s; __syncthreads();
        for (int o = 128; o > 0; o >>= 1) { if (tid < o) aux[tid] += aux[tid + o]; __syncthreads(); }
        float mu = aux[0] * (1.0f / C);
        __syncthreads();
        float q = 0.f;
        for (int j = tid; j < C; j += 256) { float d = sps[j] - mu; q += d * d; }
        aux[tid] = q; __syncthreads();
        for (int o = 128; o > 0; o >>= 1) { if (tid < o) aux[tid] += aux[tid + o]; __syncthreads(); }
        float inv = 1.0f / sqrtf(aux[0] * (1.0f / C) + LN_EPS);
        for (int j = tid; j < C; j += 256)
            d_ca[b * C + j] = (sps[j] - mu) * inv * ln_g[j] + ln_b[j];
    }
    grid_bar();

    // ---- phase E: sumpar — blocks 0..127: b = blk&7, c0 = (blk>>3)*32 ----
    if (blk < 128) {
        int b = blk & 7, c0 = (blk >> 3) * 32;
        for (int i = tid; i < P; i += 256) sps[i] = d_sp[b * P + i];
        __syncthreads();
        #pragma unroll
        for (int t = 0; t < 4; t++) {
            int c = c0 + wd + t * 8;
            float ca = d_ca[b * C + c];
            float s = 0.f;
            #pragma unroll 8
            for (int i = lane; i < P; i += 32)
                s += floorf((sps[i] + ca) * 0.5f);
            s = warp_red(s);
            if (lane == 0) d_sumpar[b * C + c] = s;
        }
    }
    grid_bar();

    // ---- phase F: sel1 ----
    {
        int b = blk & 7, jg = blk >> 3;
        float ssp = d_ssp[b];
        for (int i = tid; i < C; i += 256)
            sps[i] = (d_ca[b * C + i] * ssp + d_sumpar[b * C + i]) * (1.0f / P);
        __syncthreads();
        int j = jg * 8 + wd;
        const float* wr = sk_w1 + (size_t)j * C;
        float acc = 0.f;
        #pragma unroll
        for (int k = 0; k < C / 32; k++) acc += sps[lane + 32 * k] * wr[lane + 32 * k];
        acc = warp_red(acc);
        if (lane == 0) d_s1[b * CH + j] = fmaxf(acc, 0.f);
    }
    grid_bar();

    // ---- phase G: sel2 — each warp does 2 outputs ----
    {
        int b = blk & 7, jg = blk >> 3;
        for (int i = tid; i < CH; i += 256) sps[i] = d_s1[b * CH + i];
        __syncthreads();
        #pragma unroll
        for (int h = 0; h < 2; h++) {
            int j = jg * 16 + h * 8 + wd;
            const float* wr = sk_w2 + (size_t)j * CH;
            float acc = 0.f;
            #pragma unroll
            for (int k = 0; k < CH / 32; k++) acc += sps[lane + 32 * k] * wr[lane + 32 * k];
            acc = warp_red(acc);
            if (lane == 0) d_u2[b * C + j] = fmaxf(acc, 0.f);
        }
    }
    grid_bar();

    // ---- phase H: softmax + S — blocks 0..7 ----
    if (blk < 8) {
        int b = blk;
        for (int j = tid; j < C; j += 256) sps[j] = d_u2[b * C + j];
        __syncthreads();
        float m = -1e30f;
        for (int j = tid; j < C; j += 256) m = fmaxf(m, sps[j]);
        aux[tid] = m; __syncthreads();
        for (int o = 128; o > 0; o >>= 1) { if (tid < o) aux[tid] = fmaxf(aux[tid], aux[tid + o]); __syncthreads(); }
        m = aux[0];
        __syncthreads();
        float es = 0.f;
        for (int j = tid; j < C; j += 256) es += expf(sps[j] - m);
        aux[tid] = es; __syncthreads();
        for (int o = 128; o > 0; o >>= 1) { if (tid < o) aux[tid] += aux[tid + o]; __syncthreads(); }
        float denom = aux[0];
        float ssp = d_ssp[b];
        for (int j = tid; j < C; j += 256) {
            float a = expf(sps[j] - m) / denom;
            float ca = d_ca[b * C + j];
            d_a[b * C + j] = a;
            d_S[b * C + j] = a * ca * ssp + (1.0f - a) * d_sumpar[b * C + j];
        }
    }
}

// ---------------------------------------------------------------------------
__global__ void __launch_bounds__(256, 2) k_gemm(const float* __restrict__ x,
                                                 float* __restrict__ out) {
    extern __shared__ char smem[];
    const int tid = threadIdx.x;
    const int lane = tid & 31;
    const int wid = tid >> 5;
    const int warp_m = wid >> 2;
    const int warp_n = wid & 3;
    const int b  = blockIdx.z;
    const int p0 = blockIdx.x * TN;
    const int o0 = blockIdx.y * TM;

    const uint32_t sbase = smem_u32(smem);
    const __half* wh = d_wh + (size_t)o0 * C;
    const __half* xh = d_xh + ((size_t)b * P + p0) * C;

    const int ldr = tid >> 2;
    const int ldc = tid & 3;

    float acc[4][4][4];
    #pragma unroll
    for (int i = 0; i < 4; i++)
        #pragma unroll
        for (int j = 0; j < 4; j++)
            #pragma unroll
            for (int k = 0; k < 4; k++) acc[i][j][k] = 0.f;

    auto load_stage = [&](int s) {
        const uint32_t sb = sbase + (s & (NPIPE - 1)) * STAGE_BYTES;
        const int k0 = s * KS;
        #pragma unroll
        for (int t = 0; t < 2; t++) {
            int r = ldr + t * 64;
            uint32_t soff = (uint32_t)(r * RSB + ldc * 16);
            size_t go = (size_t)r * C + k0 + ldc * 8;
            CP16(sb + OFF_A + soff, wh + go);
            CP16(sb + OFF_B + soff, xh + go);
        }
    };

    load_stage(0); CP_COMMIT();
    load_stage(1); CP_COMMIT();
    load_stage(2); CP_COMMIT();

    for (int s = 0; s < NSTAGE; s++) {
        CP_WAIT(2);
        __syncthreads();
        if (s + 3 < NSTAGE) load_stage(s + 3);
        CP_COMMIT();

        const uint32_t sb = sbase + (s & (NPIPE - 1)) * STAGE_BYTES;
        #pragma unroll
        for (int kp = 0; kp < KS / 16; kp++) {
            const uint32_t colb = (uint32_t)(kp * 32 + (lane >> 4) * 16);
            uint32_t bh[8];
            #pragma unroll
            for (int g = 0; g < 2; g++) {
                uint32_t row = (uint32_t)(warp_n * 32 + g * 16 + (lane & 15));
                uint32_t r0, r1, r2, r3;
                ldsm_x4(r0, r1, r2, r3, sb + OFF_B + row * RSB + colb);
                bh[g*4+0] = r0; bh[g*4+1] = r2; bh[g*4+2] = r1; bh[g*4+3] = r3;
            }
            #pragma unroll
            for (int fm = 0; fm < 4; fm++) {
                uint32_t row = (uint32_t)(warp_m * 64 + fm * 16 + (lane & 15));
                uint32_t ah[4];
                ldsm_x4(ah[0], ah[1], ah[2], ah[3], sb + OFF_A + row * RSB + colb);
                #pragma unroll
                for (int j = 0; j < 4; j++) {
                    int g = j >> 1, q = j & 1;
                    mma16816(acc[fm][j], ah, bh[g*4 + q*2], bh[g*4 + q*2 + 1]);
                }
            }
        }
    }

    CP_WAIT(0);
    __syncthreads();
    float* tile = reinterpret_cast<float*>(smem);
    float* sps  = tile + 128 * TEP;
    #pragma unroll
    for (int fm = 0; fm < 4; fm++) {
        int ro = warp_m * 64 + fm * 16 + (lane >> 2);
        #pragma unroll
        for (int h = 0; h < 2; h++) {
            int ol = ro + h * 8;
            #pragma unroll
            for (int j = 0; j < 4; j++) {
                int pl = warp_n * 32 + j * 8 + (lane & 3) * 2;
                tile[ol * TEP + pl]     = acc[fm][j][h*2];
                tile[ol * TEP + pl + 1] = acc[fm][j][h*2+1];
            }
        }
    }
    if (tid < 128) sps[tid] = d_sp[b * P + p0 + tid];
    __syncthreads();

    const float* xb = x + (size_t)b * C * P;
    float* ob = out + (size_t)b * C * P;
    const int p_local = tid & 127;
    const int o_half  = tid >> 7;
    const float spv = sps[p_local];
    #pragma unroll 4
    for (int it = 0; it < 64; it++) {
        int ol = it * 2 + o_half;
        int o = o0 + ol;
        float a  = d_a[b * C + o];
        float ca = d_ca[b * C + o];
        float S  = d_S[b * C + o];
        float sel = a * ca * spv + (1.0f - a) * floorf((spv + ca) * 0.5f);
        float xv = xb[(size_t)o * P + p0 + p_local];
        ob[(size_t)o * P + p0 + p_local] = tile[ol * TEP + p_local] + S + xv * sel;
    }
}

// ---------------------------------------------------------------------------
extern "C" void kernel_launch(void* const* d_in, const int* in_sizes, int n_in,
                              void* d_out, int out_size) {
    const float* x       = (const float*)d_in[0];
    const float* w_b1    = (const float*)d_in[1];
    const float* b_b1    = (const float*)d_in[2];
    const float* w_b2    = (const float*)d_in[3];
    const float* b_b2    = (const float*)d_in[4];
    const float* w_conv1 = (const float*)d_in[5];
    const float* ln_g    = (const float*)d_in[6];
    const float* ln_b    = (const float*)d_in[7];
    const float* sk_w1   = (const float*)d_in[8];
    const float* sk_w2   = (const float*)d_in[9];
    const float* res_w   = (const float*)d_in[10];
    float* out = (float*)d_out;

    static cudaStream_t s2 = nullptr;
    static cudaEvent_t eFork = nullptr, eW = nullptr;
    if (s2 == nullptr) {
        cudaStreamCreateWithFlags(&s2, cudaStreamNonBlocking);
        cudaEventCreateWithFlags(&eFork, cudaEventDisableTiming);
        cudaEventCreateWithFlags(&eW,    cudaEventDisableTiming);
        cudaFuncSetAttribute(k_gemm, cudaFuncAttributeMaxDynamicSharedMemorySize,
                             SMEM_GEMM_BYTES);
    }

    // convert_w overlaps xpass + fused chain
    cudaEventRecord(eFork, 0);
    cudaStreamWaitEvent(s2, eFork, 0);
    k_convert_w<<<C * C / 256, 256, 0, s2>>>(res_w);
    cudaEventRecord(eW, s2);

    k_xpass<<<dim3(P / 32, C / 32, B), dim3(32, 8)>>>(x, w_conv1);
    k_fused<<<NBLK, 256>>>(w_b1, b_b1, w_b2, b_b2, ln_g, ln_b, sk_w1, sk_w2);

    cudaStreamWaitEvent(0, eW, 0);
    k_gemm<<<dim3(P / TN, C / TM, B), 256, SMEM_GEMM_BYTES>>>(x, out);
}

// round 17
// speedup vs baseline: 1.0844x; 1.0844x over previous
#include <cuda_runtime.h>
#include <cuda_fp16.h>
#include <math.h>
#include <stdint.h>

#define B   8
#define C   512
#define CH  256
#define P   4096
#define LN_EPS 1e-6f

#define TM 128
#define TN 128
#define KS 32
#define NSTAGE (C / KS)
#define NPIPE 4

#define RSB 80
#define TILE_BYTES (128 * RSB)
#define OFF_A 0
#define OFF_B (TILE_BYTES)
#define STAGE_BYTES (2 * TILE_BYTES)
#define SMEM_GEMM_BYTES (NPIPE * STAGE_BYTES)  // 81920
#define TEP 132

// scratch
__device__ float d_gpart[P/32][B*C];
__device__ float d_sppart16[C/32][B*P];
__device__ float d_g[B*C];
__device__ float d_sp[B*P];
__device__ float d_ssp[B];
__device__ float d_t1[B*CH];
__device__ float d_t2[B*C];
__device__ float d_s1[B*CH];
__device__ float d_u2[B*C];
__device__ float d_ca[B*C];
__device__ float d_sumpar[B*C];
__device__ float d_a[B*C];
__device__ float d_S[B*C];
__device__ __half d_xh[(size_t)B*P*C];
__device__ __half d_wh[C*C];

__device__ __forceinline__ float hsig(float v) {
    return fminf(fmaxf((v + 3.0f) * (1.0f/6.0f), 0.0f), 1.0f);
}

__device__ __forceinline__ uint32_t smem_u32(const void* p) {
    uint32_t a;
    asm("{ .reg .u64 t; cvta.to.shared.u64 t, %1; cvt.u32.u64 %0, t; }" : "=r"(a) : "l"(p));
    return a;
}
#define CP16(dst, src) \
    asm volatile("cp.async.cg.shared.global [%0], [%1], 16;" :: "r"(dst), "l"(src))
#define CP_COMMIT() asm volatile("cp.async.commit_group;" ::: "memory")
#define CP_WAIT(n)  asm volatile("cp.async.wait_group %0;" :: "n"(n) : "memory")

__device__ __forceinline__ void ldsm_x4(uint32_t& r0, uint32_t& r1, uint32_t& r2,
                                        uint32_t& r3, uint32_t addr) {
    asm volatile("ldmatrix.sync.aligned.m8n8.x4.shared.b16 {%0,%1,%2,%3}, [%4];"
                 : "=r"(r0), "=r"(r1), "=r"(r2), "=r"(r3) : "r"(addr));
}

__device__ __forceinline__ void mma16816(float* c, const uint32_t* a,
                                         uint32_t b0, uint32_t b1) {
    asm volatile(
        "mma.sync.aligned.m16n8k16.row.col.f32.f16.f16.f32 "
        "{%0,%1,%2,%3}, {%4,%5,%6,%7}, {%8,%9}, {%0,%1,%2,%3};"
        : "+f"(c[0]), "+f"(c[1]), "+f"(c[2]), "+f"(c[3])
        : "r"(a[0]), "r"(a[1]), "r"(a[2]), "r"(a[3]), "r"(b0), "r"(b1));
}

__device__ __forceinline__ float warp_red(float v) {
    #pragma unroll
    for (int o = 16; o > 0; o >>= 1) v += __shfl_down_sync(0xffffffffu, v, o);
    return v;
}

// ---------------------------------------------------------------------------
// K_X: ONE pass over x -> xh transpose + channel-sum partials + spatial partials
__global__ void k_xpass(const float* __restrict__ x, const float* __restrict__ w1) {
    __shared__ float tile[32][33];
    __shared__ float red[8][32];
    __shared__ float w1s[32];
    int b = blockIdx.z, c0 = blockIdx.y * 32, p0 = blockIdx.x * 32;
    int tx = threadIdx.x, ty = threadIdx.y;
    if (ty == 0) w1s[tx] = w1[c0 + tx];
    #pragma unroll
    for (int i = 0; i < 4; i++) {
        int cl = ty + i * 8;
        tile[cl][tx] = x[((size_t)b * C + c0 + cl) * P + p0 + tx];
    }
    __syncthreads();
    #pragma unroll
    for (int i = 0; i < 4; i++) {
        int pl = ty + i * 8;
        d_xh[((size_t)b * P + p0 + pl) * C + c0 + tx] = __float2half(tile[tx][pl]);
    }
    #pragma unroll
    for (int i = 0; i < 4; i++) {
        int cl = ty + i * 8;
        float v = warp_red(tile[cl][tx]);
        if (tx == 0) d_gpart[blockIdx.x][b * C + c0 + cl] = v;
    }
    {
        float acc = 0.f;
        #pragma unroll
        for (int i = 0; i < 4; i++) {
            int cl = ty + i * 8;
            acc += tile[cl][tx] * w1s[cl];
        }
        red[ty][tx] = acc; __syncthreads();
        if (ty < 4) red[ty][tx] += red[ty + 4][tx];
        __syncthreads();
        if (ty < 2) red[ty][tx] += red[ty + 2][tx];
        __syncthreads();
        if (ty == 0) d_sppart16[blockIdx.y][b * P + p0 + tx] = red[0][tx] + red[1][tx];
    }
}

// K_GF: 4-way split reduction
__global__ void k_gfin() {
    __shared__ float part[4][64];
    int tid = threadIdx.x;
    int li = tid & 63, q = tid >> 6;
    int i = blockIdx.x * 64 + li;
    float s = 0.f;
    #pragma unroll
    for (int t = 0; t < 32; t++) s += d_gpart[q * 32 + t][i];
    part[q][li] = s;
    __syncthreads();
    if (q == 0) d_g[i] = part[0][li] + part[1][li] + part[2][li] + part[3][li];
}

__global__ void k_spfin_ssp() {
    int b = blockIdx.x, tid = threadIdx.x;
    __shared__ float sh[512];
    float s = 0.f;
    #pragma unroll
    for (int t = 0; t < P / 512; t++) {
        int i = b * P + t * 512 + tid;
        float v = 0.f;
        #pragma unroll
        for (int q = 0; q < C / 32; q++) v += d_sppart16[q][i];
        v = hsig(v);
        d_sp[i] = v;
        s += v;
    }
    sh[tid] = s; __syncthreads();
    for (int o = 256; o > 0; o >>= 1) { if (tid < o) sh[tid] += sh[tid + o]; __syncthreads(); }
    if (tid == 0) d_ssp[b] = sh[0];
}

__global__ void k_convert_w(const float* __restrict__ res_w) {
    int i = blockIdx.x * 256 + threadIdx.x;
    d_wh[i] = __float2half(res_w[i]);
}

// ---------------------------------------------------------------------------
__global__ void k_mlp1(const float* __restrict__ w_b1, const float* __restrict__ b_b1) {
    __shared__ float g[C];
    int b = blockIdx.y;
    int tid = threadIdx.x, wd = tid >> 5, lane = tid & 31;
    for (int i = tid; i < C; i += 256) g[i] = d_g[b * C + i] * (1.0f / P);
    __syncthreads();
    int j = blockIdx.x * 8 + wd;
    const float* wr = w_b1 + (size_t)j * C;
    float acc = 0.f;
    #pragma unroll
    for (int k = 0; k < C / 32; k++) acc += g[lane + 32 * k] * wr[lane + 32 * k];
    acc = warp_red(acc);
    if (lane == 0) d_t1[b * CH + j] = fmaxf(acc + b_b1[j], 0.f);
}

__global__ void k_mlp2(const float* __restrict__ w_b2, const float* __restrict__ b_b2) {
    __shared__ float t1[CH];
    int b = blockIdx.y;
    int tid = threadIdx.x, wd = tid >> 5, lane = tid & 31;
    for (int i = tid; i < CH; i += 256) t1[i] = d_t1[b * CH + i];
    __syncthreads();
    int j = blockIdx.x * 8 + wd;
    const float* wr = w_b2 + (size_t)j * CH;
    float acc = 0.f;
    #pragma unroll
    for (int k = 0; k < CH / 32; k++) acc += t1[lane + 32 * k] * wr[lane + 32 * k];
    acc = warp_red(acc);
    if (lane == 0) d_t2[b * C + j] = hsig(acc + b_b2[j]);
}

__global__ void k_ln(const float* __restrict__ ln_g, const float* __restrict__ ln_b) {
    int b = blockIdx.x, tid = threadIdx.x;
    __shared__ float t2[C];
    __shared__ float red[256];
    for (int j = tid; j < C; j += 256) t2[j] = d_t2[b * C + j];
    __syncthreads();
    float s = 0.f;
    for (int j = tid; j < C; j += 256) s += t2[j];
    red[tid] = s; __syncthreads();
    for (int o = 128; o > 0; o >>= 1) { if (tid < o) red[tid] += red[tid + o]; __syncthreads(); }
    float mu = red[0] * (1.0f / C);
    __syncthreads();
    float q = 0.f;
    for (int j = tid; j < C; j += 256) { float d = t2[j] - mu; q += d * d; }
    red[tid] = q; __syncthreads();
    for (int o = 128; o > 0; o >>= 1) { if (tid < o) red[tid] += red[tid + o]; __syncthreads(); }
    float inv = 1.0f / sqrtf(red[0] * (1.0f / C) + LN_EPS);
    for (int j = tid; j < C; j += 256)
        d_ca[b * C + j] = (t2[j] - mu) * inv * ln_g[j] + ln_b[j];
}

// K4: tiled sumpar
__global__ void k_sumpar() {
    __shared__ float sps[P];
    int b = blockIdx.y, c0 = blockIdx.x * 32;
    int tid = threadIdx.x, wd = tid >> 5, lane = tid & 31;
    for (int i = tid; i < P; i += 256) sps[i] = d_sp[b * P + i];
    __syncthreads();
    #pragma unroll
    for (int t = 0; t < 4; t++) {
        int c = c0 + wd + t * 8;
        float ca = d_ca[b * C + c];
        float s = 0.f;
        #pragma unroll 8
        for (int i = lane; i < P; i += 32)
            s += floorf((sps[i] + ca) * 0.5f);
        s = warp_red(s);
        if (lane == 0) d_sumpar[b * C + c] = s;
    }
}

__global__ void k_sel1(const float* __restrict__ sk_w1) {
    __shared__ float u[C];
    int b = blockIdx.y;
    int tid = threadIdx.x, wd = tid >> 5, lane = tid & 31;
    float ssp = d_ssp[b];
    for (int i = tid; i < C; i += 256)
        u[i] = (d_ca[b * C + i] * ssp + d_sumpar[b * C + i]) * (1.0f / P);
    __syncthreads();
    int j = blockIdx.x * 8 + wd;
    const float* wr = sk_w1 + (size_t)j * C;
    float acc = 0.f;
    #pragma unroll
    for (int k = 0; k < C / 32; k++) acc += u[lane + 32 * k] * wr[lane + 32 * k];
    acc = warp_red(acc);
    if (lane == 0) d_s1[b * CH + j] = fmaxf(acc, 0.f);
}

__global__ void k_sel2(const float* __restrict__ sk_w2) {
    __shared__ float s1[CH];
    int b = blockIdx.y;
    int tid = threadIdx.x, wd = tid >> 5, lane = tid & 31;
    for (int i = tid; i < CH; i += 256) s1[i] = d_s1[b * CH + i];
    __syncthreads();
    int j = blockIdx.x * 8 + wd;
    const float* wr = sk_w2 + (size_t)j * CH;
    float acc = 0.f;
    #pragma unroll
    for (int k = 0; k < CH / 32; k++) acc += s1[lane + 32 * k] * wr[lane + 32 * k];
    acc = warp_red(acc);
    if (lane == 0) d_u2[b * C + j] = fmaxf(acc, 0.f);
}

__global__ void k_sel3() {
    int b = blockIdx.x, tid = threadIdx.x;
    __shared__ float u2[C];
    __shared__ float red[256];
    for (int j = tid; j < C; j += 256) u2[j] = d_u2[b * C + j];
    __syncthreads();
    float m = -1e30f;
    for (int j = tid; j < C; j += 256) m = fmaxf(m, u2[j]);
    red[tid] = m; __syncthreads();
    for (int o = 128; o > 0; o >>= 1) { if (tid < o) red[tid] = fmaxf(red[tid], red[tid + o]); __syncthreads(); }
    m = red[0];
    __syncthreads();
    float es = 0.f;
    for (int j = tid; j < C; j += 256) es += expf(u2[j] - m);
    red[tid] = es; __syncthreads();
    for (int o = 128; o > 0; o >>= 1) { if (tid < o) red[tid] += red[tid + o]; __syncthreads(); }
    float denom = red[0];
    float ssp = d_ssp[b];
    for (int j = tid; j < C; j += 256) {
        float a = expf(u2[j] - m) / denom;
        float ca = d_ca[b * C + j];
        d_a[b * C + j] = a;
        d_S[b * C + j] = a * ca * ssp + (1.0f - a) * d_sumpar[b * C + j];
    }
}

// ---------------------------------------------------------------------------
// K6: fp16 mma.sync GEMM — all fragment loads hoisted before the MMA burst
__global__ void __launch_bounds__(256, 2) k_gemm(const float* __restrict__ x,
                                                 float* __restrict__ out) {
    extern __shared__ char smem[];
    const int tid = threadIdx.x;
    const int lane = tid & 31;
    const int wid = tid >> 5;
    const int warp_m = wid >> 2;
    const int warp_n = wid & 3;
    const int b  = blockIdx.z;
    const int p0 = blockIdx.x * TN;
    const int o0 = blockIdx.y * TM;

    const uint32_t sbase = smem_u32(smem);
    const __half* wh = d_wh + (size_t)o0 * C;
    const __half* xh = d_xh + ((size_t)b * P + p0) * C;

    const int ldr = tid >> 2;
    const int ldc = tid & 3;

    float acc[4][4][4];
    #pragma unroll
    for (int i = 0; i < 4; i++)
        #pragma unroll
        for (int j = 0; j < 4; j++)
            #pragma unroll
            for (int k = 0; k < 4; k++) acc[i][j][k] = 0.f;

    auto load_stage = [&](int s) {
        const uint32_t sb = sbase + (s & (NPIPE - 1)) * STAGE_BYTES;
        const int k0 = s * KS;
        #pragma unroll
        for (int t = 0; t < 2; t++) {
            int r = ldr + t * 64;
            uint32_t soff = (uint32_t)(r * RSB + ldc * 16);
            size_t go = (size_t)r * C + k0 + ldc * 8;
            CP16(sb + OFF_A + soff, wh + go);
            CP16(sb + OFF_B + soff, xh + go);
        }
    };

    load_stage(0); CP_COMMIT();
    load_stage(1); CP_COMMIT();
    load_stage(2); CP_COMMIT();

    for (int s = 0; s < NSTAGE; s++) {
        CP_WAIT(2);
        __syncthreads();
        if (s + 3 < NSTAGE) load_stage(s + 3);
        CP_COMMIT();

        const uint32_t sb = sbase + (s & (NPIPE - 1)) * STAGE_BYTES;
        #pragma unroll
        for (int kp = 0; kp < KS / 16; kp++) {
            const uint32_t colb = (uint32_t)(kp * 32 + (lane >> 4) * 16);
            // hoist ALL fragment loads: 2 B-ldsm + 4 A-ldsm, fully independent
            uint32_t bh[8];
            uint32_t ah[4][4];
            #pragma unroll
            for (int g = 0; g < 2; g++) {
                uint32_t row = (uint32_t)(warp_n * 32 + g * 16 + (lane & 15));
                uint32_t r0, r1, r2, r3;
                ldsm_x4(r0, r1, r2, r3, sb + OFF_B + row * RSB + colb);
                bh[g*4+0] = r0; bh[g*4+1] = r2; bh[g*4+2] = r1; bh[g*4+3] = r3;
            }
            #pragma unroll
            for (int fm = 0; fm < 4; fm++) {
                uint32_t row = (uint32_t)(warp_m * 64 + fm * 16 + (lane & 15));
                ldsm_x4(ah[fm][0], ah[fm][1], ah[fm][2], ah[fm][3],
                        sb + OFF_A + row * RSB + colb);
            }
            // 16 back-to-back MMAs, no intervening shared loads
            #pragma unroll
            for (int fm = 0; fm < 4; fm++) {
                #pragma unroll
                for (int j = 0; j < 4; j++) {
                    int g = j >> 1, q = j & 1;
                    mma16816(acc[fm][j], ah[fm], bh[g*4 + q*2], bh[g*4 + q*2 + 1]);
                }
            }
        }
    }

    CP_WAIT(0);
    __syncthreads();
    float* tile = reinterpret_cast<float*>(smem);
    float* sps  = tile + 128 * TEP;
    #pragma unroll
    for (int fm = 0; fm < 4; fm++) {
        int ro = warp_m * 64 + fm * 16 + (lane >> 2);
        #pragma unroll
        for (int h = 0; h < 2; h++) {
            int ol = ro + h * 8;
            #pragma unroll
            for (int j = 0; j < 4; j++) {
                int pl = warp_n * 32 + j * 8 + (lane & 3) * 2;
                tile[ol * TEP + pl]     = acc[fm][j][h*2];
                tile[ol * TEP + pl + 1] = acc[fm][j][h*2+1];
            }
        }
    }
    if (tid < 128) sps[tid] = d_sp[b * P + p0 + tid];
    __syncthreads();

    const float* xb = x + (size_t)b * C * P;
    float* ob = out + (size_t)b * C * P;
    const int p_local = tid & 127;
    const int o_half  = tid >> 7;
    const float spv = sps[p_local];
    #pragma unroll 4
    for (int it = 0; it < 64; it++) {
        int ol = it * 2 + o_half;
        int o = o0 + ol;
        float a  = d_a[b * C + o];
        float ca = d_ca[b * C + o];
        float S  = d_S[b * C + o];
        float sel = a * ca * spv + (1.0f - a) * floorf((spv + ca) * 0.5f);
        float xv = xb[(size_t)o * P + p0 + p_local];
        ob[(size_t)o * P + p0 + p_local] = tile[ol * TEP + p_local] + S + xv * sel;
    }
}

// ---------------------------------------------------------------------------
extern "C" void kernel_launch(void* const* d_in, const int* in_sizes, int n_in,
                              void* d_out, int out_size) {
    const float* x       = (const float*)d_in[0];
    const float* w_b1    = (const float*)d_in[1];
    const float* b_b1    = (const float*)d_in[2];
    const float* w_b2    = (const float*)d_in[3];
    const float* b_b2    = (const float*)d_in[4];
    const float* w_conv1 = (const float*)d_in[5];
    const float* ln_g    = (const float*)d_in[6];
    const float* ln_b    = (const float*)d_in[7];
    const float* sk_w1   = (const float*)d_in[8];
    const float* sk_w2   = (const float*)d_in[9];
    const float* res_w   = (const float*)d_in[10];
    float* out = (float*)d_out;

    static cudaStream_t s1 = nullptr, s2 = nullptr;
    static cudaEvent_t eFork = nullptr, eX = nullptr, eSp = nullptr, eW = nullptr;
    if (s1 == nullptr) {
        cudaStreamCreateWithFlags(&s1, cudaStreamNonBlocking);
        cudaStreamCreateWithFlags(&s2, cudaStreamNonBlocking);
        cudaEventCreateWithFlags(&eFork, cudaEventDisableTiming);
        cudaEventCreateWithFlags(&eX,    cudaEventDisableTiming);
        cudaEventCreateWithFlags(&eSp,   cudaEventDisableTiming);
        cudaEventCreateWithFlags(&eW,    cudaEventDisableTiming);
        cudaFuncSetAttribute(k_gemm, cudaFuncAttributeMaxDynamicSharedMemorySize,
                             SMEM_GEMM_BYTES);
    }

    // fork: convert_w independent
    cudaEventRecord(eFork, 0);
    cudaStreamWaitEvent(s2, eFork, 0);
    k_convert_w<<<C * C / 256, 256, 0, s2>>>(res_w);
    cudaEventRecord(eW, s2);

    // main: single pass over x
    k_xpass<<<dim3(P / 32, C / 32, B), dim3(32, 8)>>>(x, w_conv1);
    cudaEventRecord(eX, 0);

    // side stream 1: spatial finish (hides under MLP chain)
    cudaStreamWaitEvent(s1, eX, 0);
    k_spfin_ssp<<<B, 512, 0, s1>>>();
    cudaEventRecord(eSp, s1);

    // main: channel-attention chain
    k_gfin<<<B * C / 64, 256>>>();
    k_mlp1<<<dim3(CH / 8, B), 256>>>(w_b1, b_b1);
    k_mlp2<<<dim3(C / 8, B), 256>>>(w_b2, b_b2);
    k_ln<<<B, 256>>>(ln_g, ln_b);

    // join sp, then selection chain
    cudaStreamWaitEvent(0, eSp, 0);
    k_sumpar<<<dim3(C / 32, B), 256>>>();
    k_sel1<<<dim3(CH / 8, B), 256>>>(sk_w1);
    k_sel2<<<dim3(C / 8, B), 256>>>(sk_w2);
    k_sel3<<<B, 256>>>();

    // join wh, then GEMM
    cudaStreamWaitEvent(0, eW, 0);
    k_gemm<<<dim3(P / TN, C / TM, B), 256, SMEM_GEMM_BYTES>>>(x, out);
}